// round 15
// baseline (speedup 1.0000x reference)
#include <cuda_runtime.h>
#include <cuda_bf16.h>

// Problem shape (fixed by reference setup_inputs): B=8, N=8192, D=512.
// out[b, n]     = dot(s_bn, h_rl_bn) / (max(||s||,eps) * max(||h_rl||,eps))
// out[b, N + n] = dot(s_bn, h_fk_bn) / (max(||s||,eps) * max(||h_fk||,eps))
//
// Pure streaming: 402MB compulsory reads -> LTS-cap bound (~6.9TB/s).
// Structure (distilled R1-R10): two adjacent rows per warp, ALL 24 LDG.128
// front-batched, .cs loads/stores. This round: the two rows' reductions are
// INTERLEAVED -- one FMA pass over 10 accumulators, one shuffle tree at ILP
// 10 -- halving the memory-idle tail per warp; outputs for the row pair are
// adjacent, so lane 0 issues two STG.64 (float2) instead of four STG.32.

#define D_DIM  512
#define N_DIM  8192          // power of two -> row/N is a shift
#define EPS    1e-12f

__global__ __launch_bounds__(256, 2)
void cosine_rows2i_kernel(const float* __restrict__ s,
                          const float* __restrict__ h_rl,
                          const float* __restrict__ h_fk,
                          float* __restrict__ out,
                          int n_rows)
{
    const int warps_per_block = blockDim.x >> 5;
    const int warp = blockIdx.x * warps_per_block + (threadIdx.x >> 5);
    const int lane = threadIdx.x & 31;

    const int row0 = warp * 2;            // always even
    if (row0 >= n_rows) return;

    const size_t base0 = (size_t)row0 * D_DIM;
    const float4* __restrict__ s40 = (const float4*)(s    + base0);
    const float4* __restrict__ r40 = (const float4*)(h_rl + base0);
    const float4* __restrict__ f40 = (const float4*)(h_fk + base0);
    const float4* __restrict__ s41 = s40 + (D_DIM / 4);
    const float4* __restrict__ r41 = r40 + (D_DIM / 4);
    const float4* __restrict__ f41 = f40 + (D_DIM / 4);

    // n_rows = 65536 is even, so row1 = row0+1 is always valid for this
    // problem; keep a cheap guard that doesn't break the batch when true.
    const bool have1 = (row0 + 1 < n_rows);

    // Front-batch ALL 24 independent LDG.128 before any arithmetic.
    float4 a0[4], r0[4], f0[4], a1[4], r1[4], f1[4];
    #pragma unroll
    for (int i = 0; i < 4; i++) a0[i] = __ldcs(&s40[lane + i * 32]);
    #pragma unroll
    for (int i = 0; i < 4; i++) r0[i] = __ldcs(&r40[lane + i * 32]);
    #pragma unroll
    for (int i = 0; i < 4; i++) f0[i] = __ldcs(&f40[lane + i * 32]);
    if (have1) {
        #pragma unroll
        for (int i = 0; i < 4; i++) a1[i] = __ldcs(&s41[lane + i * 32]);
        #pragma unroll
        for (int i = 0; i < 4; i++) r1[i] = __ldcs(&r41[lane + i * 32]);
        #pragma unroll
        for (int i = 0; i < 4; i++) f1[i] = __ldcs(&f41[lane + i * 32]);
    } else {
        #pragma unroll
        for (int i = 0; i < 4; i++) {
            a1[i] = make_float4(0.f, 0.f, 0.f, 0.f);
            r1[i] = make_float4(0.f, 0.f, 0.f, 0.f);
            f1[i] = make_float4(0.f, 0.f, 0.f, 0.f);
        }
    }

    // Interleaved FMA pass: 10 independent accumulators (5 per row).
    float ss0 = 0.f, rr0 = 0.f, ff0 = 0.f, sr0 = 0.f, sf0 = 0.f;
    float ss1 = 0.f, rr1 = 0.f, ff1 = 0.f, sr1 = 0.f, sf1 = 0.f;

    #pragma unroll
    for (int i = 0; i < 4; i++) {
        const float4 a = a0[i], r = r0[i], f = f0[i];
        const float4 A = a1[i], R = r1[i], F = f1[i];
        ss0 = fmaf(a.x, a.x, ss0); ss0 = fmaf(a.y, a.y, ss0);
        ss0 = fmaf(a.z, a.z, ss0); ss0 = fmaf(a.w, a.w, ss0);
        ss1 = fmaf(A.x, A.x, ss1); ss1 = fmaf(A.y, A.y, ss1);
        ss1 = fmaf(A.z, A.z, ss1); ss1 = fmaf(A.w, A.w, ss1);
        rr0 = fmaf(r.x, r.x, rr0); rr0 = fmaf(r.y, r.y, rr0);
        rr0 = fmaf(r.z, r.z, rr0); rr0 = fmaf(r.w, r.w, rr0);
        rr1 = fmaf(R.x, R.x, rr1); rr1 = fmaf(R.y, R.y, rr1);
        rr1 = fmaf(R.z, R.z, rr1); rr1 = fmaf(R.w, R.w, rr1);
        ff0 = fmaf(f.x, f.x, ff0); ff0 = fmaf(f.y, f.y, ff0);
        ff0 = fmaf(f.z, f.z, ff0); ff0 = fmaf(f.w, f.w, ff0);
        ff1 = fmaf(F.x, F.x, ff1); ff1 = fmaf(F.y, F.y, ff1);
        ff1 = fmaf(F.z, F.z, ff1); ff1 = fmaf(F.w, F.w, ff1);
        sr0 = fmaf(a.x, r.x, sr0); sr0 = fmaf(a.y, r.y, sr0);
        sr0 = fmaf(a.z, r.z, sr0); sr0 = fmaf(a.w, r.w, sr0);
        sr1 = fmaf(A.x, R.x, sr1); sr1 = fmaf(A.y, R.y, sr1);
        sr1 = fmaf(A.z, R.z, sr1); sr1 = fmaf(A.w, R.w, sr1);
        sf0 = fmaf(a.x, f.x, sf0); sf0 = fmaf(a.y, f.y, sf0);
        sf0 = fmaf(a.z, f.z, sf0); sf0 = fmaf(a.w, f.w, sf0);
        sf1 = fmaf(A.x, F.x, sf1); sf1 = fmaf(A.y, F.y, sf1);
        sf1 = fmaf(A.z, F.z, sf1); sf1 = fmaf(A.w, F.w, sf1);
    }

    // One butterfly tree over all 10 partials: 5 stages, ILP 10 per stage.
    #pragma unroll
    for (int off = 16; off > 0; off >>= 1) {
        ss0 += __shfl_xor_sync(0xFFFFFFFFu, ss0, off);
        ss1 += __shfl_xor_sync(0xFFFFFFFFu, ss1, off);
        rr0 += __shfl_xor_sync(0xFFFFFFFFu, rr0, off);
        rr1 += __shfl_xor_sync(0xFFFFFFFFu, rr1, off);
        ff0 += __shfl_xor_sync(0xFFFFFFFFu, ff0, off);
        ff1 += __shfl_xor_sync(0xFFFFFFFFu, ff1, off);
        sr0 += __shfl_xor_sync(0xFFFFFFFFu, sr0, off);
        sr1 += __shfl_xor_sync(0xFFFFFFFFu, sr1, off);
        sf0 += __shfl_xor_sync(0xFFFFFFFFu, sf0, off);
        sf1 += __shfl_xor_sync(0xFFFFFFFFu, sf1, off);
    }

    if (lane == 0) {
        const float ns0 = fmaxf(sqrtf(ss0), EPS);
        const float nr0 = fmaxf(sqrtf(rr0), EPS);
        const float nf0 = fmaxf(sqrtf(ff0), EPS);
        const float ns1 = fmaxf(sqrtf(ss1), EPS);
        const float nr1 = fmaxf(sqrtf(rr1), EPS);
        const float nf1 = fmaxf(sqrtf(ff1), EPS);

        const int b = row0 >> 13;            // row0 / 8192 (pair shares b: n0 even)
        const int n = row0 & (N_DIM - 1);    // even -> float2-aligned
        float* ob = out + (size_t)b * (2 * N_DIM);

        if (have1) {
            const float2 v_rl = make_float2(sr0 / (ns0 * nr0), sr1 / (ns1 * nr1));
            const float2 v_fk = make_float2(sf0 / (ns0 * nf0), sf1 / (ns1 * nf1));
            __stcs((float2*)&ob[n],         v_rl);
            __stcs((float2*)&ob[N_DIM + n], v_fk);
        } else {
            __stcs(&ob[n],         sr0 / (ns0 * nr0));
            __stcs(&ob[N_DIM + n], sf0 / (ns0 * nf0));
        }
    }
}

extern "C" void kernel_launch(void* const* d_in, const int* in_sizes, int n_in,
                              void* d_out, int out_size)
{
    const float* s    = (const float*)d_in[0];
    const float* h_rl = (const float*)d_in[1];
    const float* h_fk = (const float*)d_in[2];
    float* out = (float*)d_out;

    const int n_rows = in_sizes[0] / D_DIM;      // B*N = 65536

    const int threads = 256;                     // 8 warps -> 16 rows per block
    const int rows_per_block = 16;
    const int blocks = (n_rows + rows_per_block - 1) / rows_per_block;  // 4096
    cosine_rows2i_kernel<<<blocks, threads>>>(s, h_rl, h_fk, out, n_rows);
}